// round 3
// baseline (speedup 1.0000x reference)
#include <cuda_runtime.h>

#define D      128
#define D4     32          // D/4
#define MAXN   100000
#define MAXE   1600000
#define SCAN_B 1024
#define GR     64          // rows (nodes) per block
#define XSTR   66          // transposed Z tile stride (8B align, bank spread)

// ---------------- scratch (no allocation allowed; __device__ globals) ----------
__device__ int       g_cnt[MAXN];
__device__ int       g_rowptr[MAXN + 1];
__device__ int       g_fill[MAXN];
__device__ float     g_dis[MAXN];
__device__ int       g_bsum[256];
__device__ int       g_boff[256];
__device__ long long g_csr[MAXE];                 // [norm(f32)<<32 | src]
__device__ float     g_buf0[(size_t)MAXN * D];

// ---------------- f32x2 helpers ----------------
__device__ __forceinline__ unsigned long long pack2(float a, float b) {
    unsigned long long r;
    asm("mov.b64 %0, {%1, %2};" : "=l"(r) : "f"(a), "f"(b));
    return r;
}
__device__ __forceinline__ unsigned long long fma2(unsigned long long a,
                                                   unsigned long long b,
                                                   unsigned long long c) {
    unsigned long long d;
    asm("fma.rn.f32x2 %0, %1, %2, %3;" : "=l"(d) : "l"(a), "l"(b), "l"(c));
    return d;
}
__device__ __forceinline__ void unpack2(unsigned long long v, float& lo, float& hi) {
    asm("mov.b64 {%0, %1}, %2;" : "=f"(lo), "=f"(hi) : "l"(v));
}

// ---------------- graph preprocessing ----------------

__global__ void k_zero(int n) {
    int i = blockIdx.x * blockDim.x + threadIdx.x;
    if (i < n) g_cnt[i] = 0;
}

__global__ void k_hist(const int* __restrict__ dst, int e) {
    int i = blockIdx.x * blockDim.x + threadIdx.x;
    if (i < e) atomicAdd(&g_cnt[dst[i]], 1);
}

__global__ void k_dis(int n) {
    int i = blockIdx.x * blockDim.x + threadIdx.x;
    if (i < n) g_dis[i] = rsqrtf((float)(g_cnt[i] + 1));   // deg incl self-loop
}

__global__ void k_bsum(int n) {
    __shared__ int s[SCAN_B];
    int t = threadIdx.x;
    int i = blockIdx.x * SCAN_B + t;
    s[t] = (i < n) ? g_cnt[i] : 0;
    __syncthreads();
    for (int off = SCAN_B / 2; off > 0; off >>= 1) {
        if (t < off) s[t] += s[t + off];
        __syncthreads();
    }
    if (t == 0) g_bsum[blockIdx.x] = s[0];
}

__global__ void k_scanb(int nb) {
    __shared__ int s[256];
    int t = threadIdx.x;
    if (t < nb) s[t] = g_bsum[t];
    __syncthreads();
    if (t == 0) {
        int run = 0;
        for (int j = 0; j < nb; j++) { int v = s[j]; s[j] = run; run += v; }
    }
    __syncthreads();
    if (t < nb) g_boff[t] = s[t];
}

__global__ void k_scan(int n, int e) {
    __shared__ int s[SCAN_B];
    int t = threadIdx.x;
    int i = blockIdx.x * SCAN_B + t;
    int v = (i < n) ? g_cnt[i] : 0;
    s[t] = v;
    __syncthreads();
    for (int off = 1; off < SCAN_B; off <<= 1) {
        int x = (t >= off) ? s[t - off] : 0;
        __syncthreads();
        s[t] += x;
        __syncthreads();
    }
    if (i < n) {
        int ex = g_boff[blockIdx.x] + s[t] - v;
        g_rowptr[i] = ex;
        g_fill[i]   = ex;
    }
    if (i == 0) g_rowptr[n] = e;
}

__global__ void k_fill(const int* __restrict__ src, const int* __restrict__ dst, int e) {
    int i = blockIdx.x * blockDim.x + threadIdx.x;
    if (i >= e) return;
    int s = src[i], d = dst[i];
    int p = atomicAdd(&g_fill[d], 1);
    float nm = g_dis[s] * g_dis[d];
    long long pk = ((long long)__float_as_int(nm) << 32) | (unsigned int)s;
    g_csr[p] = pk;
}

// ---------------- fused layer: Y = act( (A_norm X) @ W + b ) ----------------
// Phase A: each warp gathers 8 node rows Z = sum(norm * X[src]) + selfnorm*X[v],
//          writes transposed into smem sXT[k*XSTR + r].
// Phase B: FFMA2 tile GEMM from smem (identical to R1 inner loop) + bias/relu.
__global__ void __launch_bounds__(256, 2)
k_layer(const float4* __restrict__ Xin, const float* __restrict__ W,
        const float* __restrict__ bias, float4* __restrict__ Y,
        int n, int relu) {
    extern __shared__ float sm[];
    float* sW  = sm;               // D*D
    float* sXT = sm + D * D;       // D * XSTR
    int t = threadIdx.x;
    int lane = t & 31;
    int wid  = t >> 5;
    int rowBase = blockIdx.x * GR;
    int rbase = wid * 8;

    {   // load W (4096 float4)
        float4* sW4 = (float4*)sW;
        const float4* W4 = (const float4*)W;
        for (int i = t; i < D * D / 4; i += 256) sW4[i] = W4[i];
    }

    // -------- Phase A: gather 8 nodes per warp --------
    for (int nd = 0; nd < 8; nd++) {
        int r = rbase + nd;
        int node = rowBase + r;
        if (node >= n) break;

        float dv = g_dis[node];
        float sn = dv * dv;                       // self-loop norm
        float4 a = Xin[(size_t)node * D4 + lane];
        float4 acc = make_float4(sn * a.x, sn * a.y, sn * a.z, sn * a.w);

        int beg = g_rowptr[node], end = g_rowptr[node + 1];
        for (int j = beg; j < end; j++) {
            long long pk = g_csr[j];              // warp-uniform broadcast
            int   s  = (int)(pk & 0xffffffffLL);
            float nm = __int_as_float((int)(pk >> 32));
            float4 b = Xin[(size_t)s * D4 + lane];
            acc.x += nm * b.x;
            acc.y += nm * b.y;
            acc.z += nm * b.z;
            acc.w += nm * b.w;
        }
        // transposed store: cols 4*lane..4*lane+3, row r
        int c0 = 4 * lane;
        sXT[(c0 + 0) * XSTR + r] = acc.x;
        sXT[(c0 + 1) * XSTR + r] = acc.y;
        sXT[(c0 + 2) * XSTR + r] = acc.z;
        sXT[(c0 + 3) * XSTR + r] = acc.w;
    }
    __syncthreads();

    // -------- Phase B: FFMA2 GEMM + bias/relu --------
    unsigned long long acc[4][4];
#pragma unroll
    for (int j = 0; j < 4; j++)
#pragma unroll
        for (int c = 0; c < 4; c++) acc[j][c] = 0ULL;

    const float4* sW4 = (const float4*)sW;
#pragma unroll 4
    for (int k = 0; k < D; k++) {
        float4 w = sW4[k * D4 + lane];
        unsigned long long wx = pack2(w.x, w.x);
        unsigned long long wy = pack2(w.y, w.y);
        unsigned long long wz = pack2(w.z, w.z);
        unsigned long long ww = pack2(w.w, w.w);
        const float* xk = sXT + k * XSTR + rbase;
#pragma unroll
        for (int j = 0; j < 4; j++) {
            unsigned long long xp = *(const unsigned long long*)(xk + 2 * j);
            acc[j][0] = fma2(xp, wx, acc[j][0]);
            acc[j][1] = fma2(xp, wy, acc[j][1]);
            acc[j][2] = fma2(xp, wz, acc[j][2]);
            acc[j][3] = fma2(xp, ww, acc[j][3]);
        }
    }

    float4 bb = ((const float4*)bias)[lane];
#pragma unroll
    for (int j = 0; j < 4; j++) {
        float4 lo4, hi4;
        unpack2(acc[j][0], lo4.x, hi4.x);
        unpack2(acc[j][1], lo4.y, hi4.y);
        unpack2(acc[j][2], lo4.z, hi4.z);
        unpack2(acc[j][3], lo4.w, hi4.w);
        lo4.x += bb.x; lo4.y += bb.y; lo4.z += bb.z; lo4.w += bb.w;
        hi4.x += bb.x; hi4.y += bb.y; hi4.z += bb.z; hi4.w += bb.w;
        if (relu) {
            lo4.x = fmaxf(lo4.x, 0.f); lo4.y = fmaxf(lo4.y, 0.f);
            lo4.z = fmaxf(lo4.z, 0.f); lo4.w = fmaxf(lo4.w, 0.f);
            hi4.x = fmaxf(hi4.x, 0.f); hi4.y = fmaxf(hi4.y, 0.f);
            hi4.z = fmaxf(hi4.z, 0.f); hi4.w = fmaxf(hi4.w, 0.f);
        }
        int r0 = rowBase + rbase + 2 * j;
        if (r0 < n)     Y[(size_t)r0 * D4 + lane]       = lo4;
        if (r0 + 1 < n) Y[(size_t)(r0 + 1) * D4 + lane] = hi4;
    }
}

// ---------------- launch ----------------
extern "C" void kernel_launch(void* const* d_in, const int* in_sizes, int n_in,
                              void* d_out, int out_size) {
    const float* x  = (const float*)d_in[0];
    const int*   ei = (const int*)d_in[1];
    const float* W1 = (const float*)d_in[2];
    const float* b1 = (const float*)d_in[3];
    const float* W2 = (const float*)d_in[4];
    const float* b2 = (const float*)d_in[5];
    const float* W3 = (const float*)d_in[6];
    const float* b3 = (const float*)d_in[7];

    int n = in_sizes[0] / D;
    int e = in_sizes[1] / 2;
    const int* src = ei;
    const int* dst = ei + e;
    int nb = (n + SCAN_B - 1) / SCAN_B;

    // graph preprocessing
    k_zero <<<(n + 255) / 256, 256>>>(n);
    k_hist <<<(e + 255) / 256, 256>>>(dst, e);
    k_dis  <<<(n + 255) / 256, 256>>>(n);
    k_bsum <<<nb, SCAN_B>>>(n);
    k_scanb<<<1, 256>>>(nb);
    k_scan <<<nb, SCAN_B>>>(n, e);
    k_fill <<<(e + 255) / 256, 256>>>(src, dst, e);

    void* p0 = nullptr;
    cudaGetSymbolAddress(&p0, g_buf0);
    float4* B0 = (float4*)p0;

    size_t smem = (size_t)(D * D + D * XSTR) * sizeof(float);   // ~97.8KB
    cudaFuncSetAttribute(k_layer, cudaFuncAttributeMaxDynamicSharedMemorySize, (int)smem);

    int gb = (n + GR - 1) / GR;

    // fused layers: Y = act((A X) W + b)
    k_layer<<<gb, 256, smem>>>((const float4*)x, W1, b1, B0, n, 1);
    k_layer<<<gb, 256, smem>>>((const float4*)B0, W2, b2, (float4*)g_buf0 == B0 ? (float4*)d_out : (float4*)d_out, n, 1);
    // NOTE: need distinct in/out buffers; use d_out as ping buffer for layer 2
    k_layer<<<gb, 256, smem>>>((const float4*)d_out, W3, b3, B0, n, 0);
    // final result currently in B0; copy to d_out
    cudaMemcpyAsync(d_out, p0, (size_t)n * D * sizeof(float), cudaMemcpyDeviceToDevice);
}

// round 5
// speedup vs baseline: 1.3957x; 1.3957x over previous
#include <cuda_runtime.h>
#include <cuda_fp16.h>

#define D      128
#define D4     32          // D/4
#define MAXN   100000
#define MAXE   1600000
#define SCAN_B 1024
#define GR     64          // GEMM rows per block
#define XSTR   66          // transposed X tile stride (bank spread + 8B align)

// ---------------- scratch (no allocation allowed; __device__ globals) ----------
__device__ int       g_cnt[MAXN];
__device__ int       g_rowptr[MAXN + 1];
__device__ int       g_fill[MAXN];
__device__ float     g_dis[MAXN];
__device__ int       g_bsum[256];
__device__ int       g_boff[256];
__device__ long long g_csr[MAXE];                 // [norm(f32)<<32 | src]
__device__ float     g_buf0[(size_t)MAXN * D];    // fp32 agg output (next layer input)
__device__ __half    g_bufH[(size_t)MAXN * D];    // fp16 GEMM output (gather source)

// ---------------- f32x2 / bit-cast helpers ----------------
__device__ __forceinline__ unsigned long long pack2(float a, float b) {
    unsigned long long r;
    asm("mov.b64 %0, {%1, %2};" : "=l"(r) : "f"(a), "f"(b));
    return r;
}
__device__ __forceinline__ unsigned long long fma2(unsigned long long a,
                                                   unsigned long long b,
                                                   unsigned long long c) {
    unsigned long long d;
    asm("fma.rn.f32x2 %0, %1, %2, %3;" : "=l"(d) : "l"(a), "l"(b), "l"(c));
    return d;
}
__device__ __forceinline__ void unpack2(unsigned long long v, float& lo, float& hi) {
    asm("mov.b64 {%0, %1}, %2;" : "=f"(lo), "=f"(hi) : "l"(v));
}
__device__ __forceinline__ unsigned int h2_as_u32(__half2 h) {
    return *reinterpret_cast<unsigned int*>(&h);
}
__device__ __forceinline__ float2 u32_as_f2(unsigned int u) {
    return __half22float2(*reinterpret_cast<__half2*>(&u));
}

// ---------------- graph preprocessing ----------------

__global__ void k_zero(int n) {
    int i = blockIdx.x * blockDim.x + threadIdx.x;
    if (i < n) g_cnt[i] = 0;
}

__global__ void k_hist(const int* __restrict__ dst, int e) {
    int i = blockIdx.x * blockDim.x + threadIdx.x;
    if (i < e) atomicAdd(&g_cnt[dst[i]], 1);
}

__global__ void k_dis(int n) {
    int i = blockIdx.x * blockDim.x + threadIdx.x;
    if (i < n) g_dis[i] = rsqrtf((float)(g_cnt[i] + 1));   // deg incl self-loop
}

__global__ void k_bsum(int n) {
    __shared__ int s[SCAN_B];
    int t = threadIdx.x;
    int i = blockIdx.x * SCAN_B + t;
    s[t] = (i < n) ? g_cnt[i] : 0;
    __syncthreads();
    for (int off = SCAN_B / 2; off > 0; off >>= 1) {
        if (t < off) s[t] += s[t + off];
        __syncthreads();
    }
    if (t == 0) g_bsum[blockIdx.x] = s[0];
}

__global__ void k_scanb(int nb) {
    __shared__ int s[256];
    int t = threadIdx.x;
    if (t < nb) s[t] = g_bsum[t];
    __syncthreads();
    if (t == 0) {
        int run = 0;
        for (int j = 0; j < nb; j++) { int v = s[j]; s[j] = run; run += v; }
    }
    __syncthreads();
    if (t < nb) g_boff[t] = s[t];
}

__global__ void k_scan(int n, int e) {
    __shared__ int s[SCAN_B];
    int t = threadIdx.x;
    int i = blockIdx.x * SCAN_B + t;
    int v = (i < n) ? g_cnt[i] : 0;
    s[t] = v;
    __syncthreads();
    for (int off = 1; off < SCAN_B; off <<= 1) {
        int x = (t >= off) ? s[t - off] : 0;
        __syncthreads();
        s[t] += x;
        __syncthreads();
    }
    if (i < n) {
        int ex = g_boff[blockIdx.x] + s[t] - v;
        g_rowptr[i] = ex;
        g_fill[i]   = ex;
    }
    if (i == 0) g_rowptr[n] = e;
}

__global__ void k_fill(const int* __restrict__ src, const int* __restrict__ dst, int e) {
    int i = blockIdx.x * blockDim.x + threadIdx.x;
    if (i >= e) return;
    int s = src[i], d = dst[i];
    int p = atomicAdd(&g_fill[d], 1);
    float nm = g_dis[s] * g_dis[d];
    long long pk = ((long long)__float_as_int(nm) << 32) | (unsigned int)s;
    g_csr[p] = pk;
}

// ---------------- GEMM: H[n,128](fp16) = X[n,128](fp32) @ W[128,128] ----------------
// fp32 FFMA2 math; epilogue converts to fp16 rows (halves gather traffic downstream).
__global__ void __launch_bounds__(256, 2)
k_gemm(const float* __restrict__ X, const float* __restrict__ W,
       __half* __restrict__ H, int n) {
    extern __shared__ float sm[];
    float* sW  = sm;               // D*D
    float* sXT = sm + D * D;       // D * XSTR
    int t = threadIdx.x;
    int rowBase = blockIdx.x * GR;

    {   // load W (4096 float4)
        float4* sW4 = (float4*)sW;
        const float4* W4 = (const float4*)W;
        for (int i = t; i < D * D / 4; i += 256) sW4[i] = W4[i];
    }
    {   // load X tile transposed
        int c  = t & (D - 1);
        int rh = t >> 7;           // 0 or 1
#pragma unroll
        for (int rr = 0; rr < GR / 2; rr++) {
            int r = rh * (GR / 2) + rr;
            int gr = rowBase + r;
            float v = (gr < n) ? X[(size_t)gr * D + c] : 0.f;
            sXT[c * XSTR + r] = v;
        }
    }
    __syncthreads();

    int lane = t & 31;
    int wid  = t >> 5;

    unsigned long long acc[4][4];
#pragma unroll
    for (int j = 0; j < 4; j++)
#pragma unroll
        for (int c = 0; c < 4; c++) acc[j][c] = 0ULL;

    const float4* sW4 = (const float4*)sW;
    int rbase = wid * 8;
#pragma unroll 4
    for (int k = 0; k < D; k++) {
        float4 w = sW4[k * D4 + lane];
        unsigned long long wx = pack2(w.x, w.x);
        unsigned long long wy = pack2(w.y, w.y);
        unsigned long long wz = pack2(w.z, w.z);
        unsigned long long ww = pack2(w.w, w.w);
        const float* xk = sXT + k * XSTR + rbase;
#pragma unroll
        for (int j = 0; j < 4; j++) {
            unsigned long long xp = *(const unsigned long long*)(xk + 2 * j);
            acc[j][0] = fma2(xp, wx, acc[j][0]);
            acc[j][1] = fma2(xp, wy, acc[j][1]);
            acc[j][2] = fma2(xp, wz, acc[j][2]);
            acc[j][3] = fma2(xp, ww, acc[j][3]);
        }
    }

#pragma unroll
    for (int j = 0; j < 4; j++) {
        float4 lo4, hi4;
        unpack2(acc[j][0], lo4.x, hi4.x);
        unpack2(acc[j][1], lo4.y, hi4.y);
        unpack2(acc[j][2], lo4.z, hi4.z);
        unpack2(acc[j][3], lo4.w, hi4.w);
        int r0 = rowBase + rbase + 2 * j;
        if (r0 < n) {
            __half2 h0 = __floats2half2_rn(lo4.x, lo4.y);
            __half2 h1 = __floats2half2_rn(lo4.z, lo4.w);
            *(uint2*)(H + (size_t)r0 * D + lane * 4) =
                make_uint2(h2_as_u32(h0), h2_as_u32(h1));
        }
        if (r0 + 1 < n) {
            __half2 h0 = __floats2half2_rn(hi4.x, hi4.y);
            __half2 h1 = __floats2half2_rn(hi4.z, hi4.w);
            *(uint2*)(H + (size_t)(r0 + 1) * D + lane * 4) =
                make_uint2(h2_as_u32(h0), h2_as_u32(h1));
        }
    }
}

// ---------------- aggregation: out[v] = act( sum norm*H[src] + selfnorm*H[v] + b )
// H is fp16 (256B/row); one warp per node; lane covers cols lane*4..lane*4+3 (8B loads).
__global__ void k_agg(const __half* __restrict__ H, const float* __restrict__ bias,
                      float4* __restrict__ O, int n, int relu) {
    int gw = (blockIdx.x * blockDim.x + threadIdx.x) >> 5;
    if (gw >= n) return;
    int lane = threadIdx.x & 31;

    float dv = g_dis[gw];
    float sn = dv * dv;                 // self-loop norm = 1/deg
    uint2 sp = *(const uint2*)(H + (size_t)gw * D + lane * 4);
    float2 s0 = u32_as_f2(sp.x);
    float2 s1 = u32_as_f2(sp.y);
    float4 acc = make_float4(sn * s0.x, sn * s0.y, sn * s1.x, sn * s1.y);

    int beg = g_rowptr[gw], end = g_rowptr[gw + 1];
    for (int j = beg; j < end; j++) {
        long long pk = g_csr[j];        // warp-uniform broadcast
        int   s  = (int)(pk & 0xffffffffLL);
        float nm = __int_as_float((int)(pk >> 32));
        uint2 hp = *(const uint2*)(H + (size_t)s * D + lane * 4);
        float2 f0 = u32_as_f2(hp.x);
        float2 f1 = u32_as_f2(hp.y);
        acc.x += nm * f0.x;
        acc.y += nm * f0.y;
        acc.z += nm * f1.x;
        acc.w += nm * f1.y;
    }

    float4 bb = ((const float4*)bias)[lane];
    acc.x += bb.x; acc.y += bb.y; acc.z += bb.z; acc.w += bb.w;
    if (relu) {
        acc.x = fmaxf(acc.x, 0.f);
        acc.y = fmaxf(acc.y, 0.f);
        acc.z = fmaxf(acc.z, 0.f);
        acc.w = fmaxf(acc.w, 0.f);
    }
    O[(size_t)gw * D4 + lane] = acc;
}

// ---------------- launch ----------------
extern "C" void kernel_launch(void* const* d_in, const int* in_sizes, int n_in,
                              void* d_out, int out_size) {
    const float* x  = (const float*)d_in[0];
    const int*   ei = (const int*)d_in[1];
    const float* W1 = (const float*)d_in[2];
    const float* b1 = (const float*)d_in[3];
    const float* W2 = (const float*)d_in[4];
    const float* b2 = (const float*)d_in[5];
    const float* W3 = (const float*)d_in[6];
    const float* b3 = (const float*)d_in[7];

    int n = in_sizes[0] / D;
    int e = in_sizes[1] / 2;
    const int* src = ei;
    const int* dst = ei + e;
    int nb = (n + SCAN_B - 1) / SCAN_B;

    // graph preprocessing
    k_zero <<<(n + 255) / 256, 256>>>(n);
    k_hist <<<(e + 255) / 256, 256>>>(dst, e);
    k_dis  <<<(n + 255) / 256, 256>>>(n);
    k_bsum <<<nb, SCAN_B>>>(n);
    k_scanb<<<1, 256>>>(nb);
    k_scan <<<nb, SCAN_B>>>(n, e);
    k_fill <<<(e + 255) / 256, 256>>>(src, dst, e);

    void *p0 = nullptr, *pH = nullptr;
    cudaGetSymbolAddress(&p0, g_buf0);
    cudaGetSymbolAddress(&pH, g_bufH);
    float*  B0 = (float*)p0;
    __half* HB = (__half*)pH;

    size_t smem = (size_t)(D * D + D * XSTR) * sizeof(float);   // ~97.8KB
    cudaFuncSetAttribute(k_gemm, cudaFuncAttributeMaxDynamicSharedMemorySize, (int)smem);

    int gb = (n + GR - 1) / GR;
    int ab = (n + 7) / 8;        // 8 warps / block

    // layer 1
    k_gemm<<<gb, 256, smem>>>(x, W1, HB, n);
    k_agg <<<ab, 256>>>(HB, b1, (float4*)B0, n, 1);
    // layer 2
    k_gemm<<<gb, 256, smem>>>(B0, W2, HB, n);
    k_agg <<<ab, 256>>>(HB, b2, (float4*)B0, n, 1);
    // layer 3
    k_gemm<<<gb, 256, smem>>>(B0, W3, HB, n);
    k_agg <<<ab, 256>>>(HB, b3, (float4*)d_out, n, 0);
}

// round 6
// speedup vs baseline: 1.4808x; 1.0610x over previous
#include <cuda_runtime.h>
#include <cuda_fp16.h>

#define D      128
#define D4     32          // D/4
#define MAXN   100000
#define MAXE   1600000
#define SCAN_B 1024
#define GR     64          // GEMM rows per block
#define XSTR   66          // transposed X tile stride (bank spread + 8B align)

// ---------------- scratch (no allocation allowed; __device__ globals) ----------
__device__ int       g_cnt[MAXN];
__device__ int       g_rowptr[MAXN + 1];
__device__ int       g_fill[MAXN];
__device__ float     g_dis[MAXN];
__device__ int       g_bsum[256];
__device__ int       g_boff[256];
__device__ long long g_csr[MAXE];                 // [norm(f32)<<32 | src]
__device__ float     g_buf0[(size_t)MAXN * D];    // fp32 agg output (next layer input)
__device__ __half    g_bufH[(size_t)MAXN * D];    // fp16 GEMM output (gather source)

// ---------------- f32x2 / bit-cast helpers ----------------
__device__ __forceinline__ unsigned long long pack2(float a, float b) {
    unsigned long long r;
    asm("mov.b64 %0, {%1, %2};" : "=l"(r) : "f"(a), "f"(b));
    return r;
}
__device__ __forceinline__ unsigned long long fma2(unsigned long long a,
                                                   unsigned long long b,
                                                   unsigned long long c) {
    unsigned long long d;
    asm("fma.rn.f32x2 %0, %1, %2, %3;" : "=l"(d) : "l"(a), "l"(b), "l"(c));
    return d;
}
__device__ __forceinline__ void unpack2(unsigned long long v, float& lo, float& hi) {
    asm("mov.b64 {%0, %1}, %2;" : "=f"(lo), "=f"(hi) : "l"(v));
}
__device__ __forceinline__ unsigned int h2_as_u32(__half2 h) {
    return *reinterpret_cast<unsigned int*>(&h);
}
__device__ __forceinline__ float2 u32_as_f2(unsigned int u) {
    return __half22float2(*reinterpret_cast<__half2*>(&u));
}

// ---------------- graph preprocessing ----------------

__global__ void k_zero(int n) {
    int i = blockIdx.x * blockDim.x + threadIdx.x;
    if (i < n) g_cnt[i] = 0;
}

__global__ void k_hist(const int* __restrict__ dst, int e) {
    int i = blockIdx.x * blockDim.x + threadIdx.x;
    if (i < e) atomicAdd(&g_cnt[dst[i]], 1);
}

__global__ void k_dis(int n) {
    int i = blockIdx.x * blockDim.x + threadIdx.x;
    if (i < n) g_dis[i] = rsqrtf((float)(g_cnt[i] + 1));   // deg incl self-loop
}

__global__ void k_bsum(int n) {
    __shared__ int s[SCAN_B];
    int t = threadIdx.x;
    int i = blockIdx.x * SCAN_B + t;
    s[t] = (i < n) ? g_cnt[i] : 0;
    __syncthreads();
    for (int off = SCAN_B / 2; off > 0; off >>= 1) {
        if (t < off) s[t] += s[t + off];
        __syncthreads();
    }
    if (t == 0) g_bsum[blockIdx.x] = s[0];
}

__global__ void k_scanb(int nb) {
    __shared__ int s[256];
    int t = threadIdx.x;
    if (t < nb) s[t] = g_bsum[t];
    __syncthreads();
    if (t == 0) {
        int run = 0;
        for (int j = 0; j < nb; j++) { int v = s[j]; s[j] = run; run += v; }
    }
    __syncthreads();
    if (t < nb) g_boff[t] = s[t];
}

__global__ void k_scan(int n, int e) {
    __shared__ int s[SCAN_B];
    int t = threadIdx.x;
    int i = blockIdx.x * SCAN_B + t;
    int v = (i < n) ? g_cnt[i] : 0;
    s[t] = v;
    __syncthreads();
    for (int off = 1; off < SCAN_B; off <<= 1) {
        int x = (t >= off) ? s[t - off] : 0;
        __syncthreads();
        s[t] += x;
        __syncthreads();
    }
    if (i < n) {
        int ex = g_boff[blockIdx.x] + s[t] - v;
        g_rowptr[i] = ex;
        g_fill[i]   = ex;
    }
    if (i == 0) g_rowptr[n] = e;
}

__global__ void k_fill(const int* __restrict__ src, const int* __restrict__ dst, int e) {
    int i = blockIdx.x * blockDim.x + threadIdx.x;
    if (i >= e) return;
    int s = src[i], d = dst[i];
    int p = atomicAdd(&g_fill[d], 1);
    float nm = g_dis[s] * g_dis[d];
    long long pk = ((long long)__float_as_int(nm) << 32) | (unsigned int)s;
    g_csr[p] = pk;
}

// ---------------- GEMM: H[n,128](fp16) = X[n,128](fp32) @ W[128,128] ----------------
__global__ void __launch_bounds__(256, 2)
k_gemm(const float* __restrict__ X, const float* __restrict__ W,
       __half* __restrict__ H, int n) {
    extern __shared__ float sm[];
    float* sW  = sm;               // D*D
    float* sXT = sm + D * D;       // D * XSTR
    int t = threadIdx.x;
    int rowBase = blockIdx.x * GR;

    {   // load W (4096 float4)
        float4* sW4 = (float4*)sW;
        const float4* W4 = (const float4*)W;
        for (int i = t; i < D * D / 4; i += 256) sW4[i] = W4[i];
    }
    {   // load X tile transposed
        int c  = t & (D - 1);
        int rh = t >> 7;           // 0 or 1
#pragma unroll
        for (int rr = 0; rr < GR / 2; rr++) {
            int r = rh * (GR / 2) + rr;
            int gr = rowBase + r;
            float v = (gr < n) ? X[(size_t)gr * D + c] : 0.f;
            sXT[c * XSTR + r] = v;
        }
    }
    __syncthreads();

    int lane = t & 31;
    int wid  = t >> 5;

    unsigned long long acc[4][4];
#pragma unroll
    for (int j = 0; j < 4; j++)
#pragma unroll
        for (int c = 0; c < 4; c++) acc[j][c] = 0ULL;

    const float4* sW4 = (const float4*)sW;
    int rbase = wid * 8;
#pragma unroll 4
    for (int k = 0; k < D; k++) {
        float4 w = sW4[k * D4 + lane];
        unsigned long long wx = pack2(w.x, w.x);
        unsigned long long wy = pack2(w.y, w.y);
        unsigned long long wz = pack2(w.z, w.z);
        unsigned long long ww = pack2(w.w, w.w);
        const float* xk = sXT + k * XSTR + rbase;
#pragma unroll
        for (int j = 0; j < 4; j++) {
            unsigned long long xp = *(const unsigned long long*)(xk + 2 * j);
            acc[j][0] = fma2(xp, wx, acc[j][0]);
            acc[j][1] = fma2(xp, wy, acc[j][1]);
            acc[j][2] = fma2(xp, wz, acc[j][2]);
            acc[j][3] = fma2(xp, ww, acc[j][3]);
        }
    }

#pragma unroll
    for (int j = 0; j < 4; j++) {
        float4 lo4, hi4;
        unpack2(acc[j][0], lo4.x, hi4.x);
        unpack2(acc[j][1], lo4.y, hi4.y);
        unpack2(acc[j][2], lo4.z, hi4.z);
        unpack2(acc[j][3], lo4.w, hi4.w);
        int r0 = rowBase + rbase + 2 * j;
        if (r0 < n) {
            __half2 h0 = __floats2half2_rn(lo4.x, lo4.y);
            __half2 h1 = __floats2half2_rn(lo4.z, lo4.w);
            *(uint2*)(H + (size_t)r0 * D + lane * 4) =
                make_uint2(h2_as_u32(h0), h2_as_u32(h1));
        }
        if (r0 + 1 < n) {
            __half2 h0 = __floats2half2_rn(hi4.x, hi4.y);
            __half2 h1 = __floats2half2_rn(hi4.z, hi4.w);
            *(uint2*)(H + (size_t)(r0 + 1) * D + lane * 4) =
                make_uint2(h2_as_u32(h0), h2_as_u32(h1));
        }
    }
}

// ---------------- aggregation (4x unrolled edge loop for MLP) ----------------
__global__ void k_agg(const __half* __restrict__ H, const float* __restrict__ bias,
                      float4* __restrict__ O, int n, int relu) {
    int gw = (blockIdx.x * blockDim.x + threadIdx.x) >> 5;
    if (gw >= n) return;
    int lane = threadIdx.x & 31;

    float dv = g_dis[gw];
    float sn = dv * dv;                 // self-loop norm = 1/deg
    uint2 sp = *(const uint2*)(H + (size_t)gw * D + lane * 4);
    float2 s0 = u32_as_f2(sp.x);
    float2 s1 = u32_as_f2(sp.y);
    float4 acc = make_float4(sn * s0.x, sn * s0.y, sn * s1.x, sn * s1.y);

    int beg = g_rowptr[gw], end = g_rowptr[gw + 1];
    int j = beg;
    // 4x unrolled: 4 independent CSR loads, then 4 independent gathers (MLP=4+)
    for (; j + 4 <= end; j += 4) {
        long long pk0 = g_csr[j + 0];
        long long pk1 = g_csr[j + 1];
        long long pk2 = g_csr[j + 2];
        long long pk3 = g_csr[j + 3];
        int s0i = (int)(pk0 & 0xffffffffLL);
        int s1i = (int)(pk1 & 0xffffffffLL);
        int s2i = (int)(pk2 & 0xffffffffLL);
        int s3i = (int)(pk3 & 0xffffffffLL);
        uint2 h0 = *(const uint2*)(H + (size_t)s0i * D + lane * 4);
        uint2 h1 = *(const uint2*)(H + (size_t)s1i * D + lane * 4);
        uint2 h2 = *(const uint2*)(H + (size_t)s2i * D + lane * 4);
        uint2 h3 = *(const uint2*)(H + (size_t)s3i * D + lane * 4);
        float nm0 = __int_as_float((int)(pk0 >> 32));
        float nm1 = __int_as_float((int)(pk1 >> 32));
        float nm2 = __int_as_float((int)(pk2 >> 32));
        float nm3 = __int_as_float((int)(pk3 >> 32));
        float2 a0 = u32_as_f2(h0.x), b0 = u32_as_f2(h0.y);
        float2 a1 = u32_as_f2(h1.x), b1 = u32_as_f2(h1.y);
        float2 a2 = u32_as_f2(h2.x), b2 = u32_as_f2(h2.y);
        float2 a3 = u32_as_f2(h3.x), b3 = u32_as_f2(h3.y);
        acc.x += nm0 * a0.x; acc.y += nm0 * a0.y; acc.z += nm0 * b0.x; acc.w += nm0 * b0.y;
        acc.x += nm1 * a1.x; acc.y += nm1 * a1.y; acc.z += nm1 * b1.x; acc.w += nm1 * b1.y;
        acc.x += nm2 * a2.x; acc.y += nm2 * a2.y; acc.z += nm2 * b2.x; acc.w += nm2 * b2.y;
        acc.x += nm3 * a3.x; acc.y += nm3 * a3.y; acc.z += nm3 * b3.x; acc.w += nm3 * b3.y;
    }
    for (; j < end; j++) {
        long long pk = g_csr[j];
        int   s  = (int)(pk & 0xffffffffLL);
        float nm = __int_as_float((int)(pk >> 32));
        uint2 hp = *(const uint2*)(H + (size_t)s * D + lane * 4);
        float2 f0 = u32_as_f2(hp.x);
        float2 f1 = u32_as_f2(hp.y);
        acc.x += nm * f0.x;
        acc.y += nm * f0.y;
        acc.z += nm * f1.x;
        acc.w += nm * f1.y;
    }

    float4 bb = ((const float4*)bias)[lane];
    acc.x += bb.x; acc.y += bb.y; acc.z += bb.z; acc.w += bb.w;
    if (relu) {
        acc.x = fmaxf(acc.x, 0.f);
        acc.y = fmaxf(acc.y, 0.f);
        acc.z = fmaxf(acc.z, 0.f);
        acc.w = fmaxf(acc.w, 0.f);
    }
    O[(size_t)gw * D4 + lane] = acc;
}

// ---------------- launch ----------------
extern "C" void kernel_launch(void* const* d_in, const int* in_sizes, int n_in,
                              void* d_out, int out_size) {
    const float* x  = (const float*)d_in[0];
    const int*   ei = (const int*)d_in[1];
    const float* W1 = (const float*)d_in[2];
    const float* b1 = (const float*)d_in[3];
    const float* W2 = (const float*)d_in[4];
    const float* b2 = (const float*)d_in[5];
    const float* W3 = (const float*)d_in[6];
    const float* b3 = (const float*)d_in[7];

    int n = in_sizes[0] / D;
    int e = in_sizes[1] / 2;
    const int* src = ei;
    const int* dst = ei + e;
    int nb = (n + SCAN_B - 1) / SCAN_B;

    // graph preprocessing
    k_zero <<<(n + 255) / 256, 256>>>(n);
    k_hist <<<(e + 255) / 256, 256>>>(dst, e);
    k_dis  <<<(n + 255) / 256, 256>>>(n);
    k_bsum <<<nb, SCAN_B>>>(n);
    k_scanb<<<1, 256>>>(nb);
    k_scan <<<nb, SCAN_B>>>(n, e);
    k_fill <<<(e + 255) / 256, 256>>>(src, dst, e);

    void *p0 = nullptr, *pH = nullptr;
    cudaGetSymbolAddress(&p0, g_buf0);
    cudaGetSymbolAddress(&pH, g_bufH);
    float*  B0 = (float*)p0;
    __half* HB = (__half*)pH;

    size_t smem = (size_t)(D * D + D * XSTR) * sizeof(float);   // ~97.8KB
    cudaFuncSetAttribute(k_gemm, cudaFuncAttributeMaxDynamicSharedMemorySize, (int)smem);

    int gb = (n + GR - 1) / GR;
    int ab = (n + 7) / 8;        // 8 warps / block

    // layer 1
    k_gemm<<<gb, 256, smem>>>(x, W1, HB, n);
    k_agg <<<ab, 256>>>(HB, b1, (float4*)B0, n, 1);
    // layer 2
    k_gemm<<<gb, 256, smem>>>(B0, W2, HB, n);
    k_agg <<<ab, 256>>>(HB, b2, (float4*)B0, n, 1);
    // layer 3
    k_gemm<<<gb, 256, smem>>>(B0, W3, HB, n);
    k_agg <<<ab, 256>>>(HB, b3, (float4*)d_out, n, 0);
}

// round 7
// speedup vs baseline: 1.4961x; 1.0104x over previous
#include <cuda_runtime.h>
#include <cuda_fp16.h>

#define D      128
#define D4     32          // D/4
#define MAXN   100000
#define MAXE   1600000
#define GR     64          // GEMM rows per block
#define XSTR   66          // transposed X tile stride (bank spread + 8B align)

// ---------------- scratch (no allocation allowed; __device__ globals) ----------
__device__ int       g_cnt[MAXN];                 // degree, then reused as row END
__device__ int       g_rowptr[MAXN];              // row START (atomic-allocated)
__device__ int       g_fill[MAXN];
__device__ float     g_dis[MAXN];
__device__ int       g_tail;                      // CSR allocation cursor
__device__ long long g_csr[MAXE];                 // [norm(f32)<<32 | src]
__device__ float     g_buf0[(size_t)MAXN * D];    // fp32 agg output (next layer input)
__device__ __half    g_bufH[(size_t)MAXN * D];    // fp16 GEMM output (gather source)

// ---------------- f32x2 / bit-cast helpers ----------------
__device__ __forceinline__ unsigned long long pack2(float a, float b) {
    unsigned long long r;
    asm("mov.b64 %0, {%1, %2};" : "=l"(r) : "f"(a), "f"(b));
    return r;
}
__device__ __forceinline__ unsigned long long fma2(unsigned long long a,
                                                   unsigned long long b,
                                                   unsigned long long c) {
    unsigned long long d;
    asm("fma.rn.f32x2 %0, %1, %2, %3;" : "=l"(d) : "l"(a), "l"(b), "l"(c));
    return d;
}
__device__ __forceinline__ void unpack2(unsigned long long v, float& lo, float& hi) {
    asm("mov.b64 {%0, %1}, %2;" : "=f"(lo), "=f"(hi) : "l"(v));
}
__device__ __forceinline__ unsigned int h2_as_u32(__half2 h) {
    return *reinterpret_cast<unsigned int*>(&h);
}
__device__ __forceinline__ float2 u32_as_f2(unsigned int u) {
    return __half22float2(*reinterpret_cast<__half2*>(&u));
}

// ---------------- graph preprocessing (3 kernels + 2 memsets) ----------------

__global__ void k_hist(const int* __restrict__ dst, int e) {
    int i = blockIdx.x * blockDim.x + threadIdx.x;
    if (i < e) atomicAdd(&g_cnt[dst[i]], 1);
}

// dis + CSR slot allocation (replaces the 3-kernel prefix scan; offsets need
// not be monotonic, only per-node contiguous).
__global__ void k_disalloc(int n) {
    int i = blockIdx.x * blockDim.x + threadIdx.x;
    if (i >= n) return;
    int c = g_cnt[i];
    g_dis[i] = rsqrtf((float)(c + 1));     // deg incl self-loop
    int base = atomicAdd(&g_tail, c);
    g_rowptr[i] = base;
    g_fill[i]   = base;
    g_cnt[i]    = base + c;                // reuse as row END
}

__global__ void k_fill(const int* __restrict__ src, const int* __restrict__ dst, int e) {
    int i = blockIdx.x * blockDim.x + threadIdx.x;
    if (i >= e) return;
    int s = src[i], d = dst[i];
    int p = atomicAdd(&g_fill[d], 1);
    float nm = g_dis[s] * g_dis[d];
    long long pk = ((long long)__float_as_int(nm) << 32) | (unsigned int)s;
    g_csr[p] = pk;
}

// ---------------- GEMM: H[n,128](fp16) = X[n,128](fp32) @ W[128,128] ----------------
__global__ void __launch_bounds__(256, 2)
k_gemm(const float* __restrict__ X, const float* __restrict__ W,
       __half* __restrict__ H, int n) {
    extern __shared__ float sm[];
    float* sW  = sm;               // D*D
    float* sXT = sm + D * D;       // D * XSTR
    int t = threadIdx.x;
    int rowBase = blockIdx.x * GR;

    {   // load W (4096 float4)
        float4* sW4 = (float4*)sW;
        const float4* W4 = (const float4*)W;
        for (int i = t; i < D * D / 4; i += 256) sW4[i] = W4[i];
    }
    {   // load X tile transposed
        int c  = t & (D - 1);
        int rh = t >> 7;           // 0 or 1
#pragma unroll
        for (int rr = 0; rr < GR / 2; rr++) {
            int r = rh * (GR / 2) + rr;
            int gr = rowBase + r;
            float v = (gr < n) ? X[(size_t)gr * D + c] : 0.f;
            sXT[c * XSTR + r] = v;
        }
    }
    __syncthreads();

    int lane = t & 31;
    int wid  = t >> 5;

    unsigned long long acc[4][4];
#pragma unroll
    for (int j = 0; j < 4; j++)
#pragma unroll
        for (int c = 0; c < 4; c++) acc[j][c] = 0ULL;

    const float4* sW4 = (const float4*)sW;
    int rbase = wid * 8;
#pragma unroll 4
    for (int k = 0; k < D; k++) {
        float4 w = sW4[k * D4 + lane];
        unsigned long long wx = pack2(w.x, w.x);
        unsigned long long wy = pack2(w.y, w.y);
        unsigned long long wz = pack2(w.z, w.z);
        unsigned long long ww = pack2(w.w, w.w);
        const float* xk = sXT + k * XSTR + rbase;
#pragma unroll
        for (int j = 0; j < 4; j++) {
            unsigned long long xp = *(const unsigned long long*)(xk + 2 * j);
            acc[j][0] = fma2(xp, wx, acc[j][0]);
            acc[j][1] = fma2(xp, wy, acc[j][1]);
            acc[j][2] = fma2(xp, wz, acc[j][2]);
            acc[j][3] = fma2(xp, ww, acc[j][3]);
        }
    }

#pragma unroll
    for (int j = 0; j < 4; j++) {
        float4 lo4, hi4;
        unpack2(acc[j][0], lo4.x, hi4.x);
        unpack2(acc[j][1], lo4.y, hi4.y);
        unpack2(acc[j][2], lo4.z, hi4.z);
        unpack2(acc[j][3], lo4.w, hi4.w);
        int r0 = rowBase + rbase + 2 * j;
        if (r0 < n) {
            __half2 h0 = __floats2half2_rn(lo4.x, lo4.y);
            __half2 h1 = __floats2half2_rn(lo4.z, lo4.w);
            *(uint2*)(H + (size_t)r0 * D + lane * 4) =
                make_uint2(h2_as_u32(h0), h2_as_u32(h1));
        }
        if (r0 + 1 < n) {
            __half2 h0 = __floats2half2_rn(hi4.x, hi4.y);
            __half2 h1 = __floats2half2_rn(hi4.z, hi4.w);
            *(uint2*)(H + (size_t)(r0 + 1) * D + lane * 4) =
                make_uint2(h2_as_u32(h0), h2_as_u32(h1));
        }
    }
}

// ---------------- aggregation (8x/4x unrolled edge loop for MLP) ----------------
#define EDGE_BODY(pk)                                                  \
    {                                                                  \
        int   si = (int)((pk) & 0xffffffffLL);                         \
        float nm = __int_as_float((int)((pk) >> 32));                  \
        uint2 hp = *(const uint2*)(H + (size_t)si * D + lane * 4);     \
        float2 f0 = u32_as_f2(hp.x);                                   \
        float2 f1 = u32_as_f2(hp.y);                                   \
        acc.x += nm * f0.x; acc.y += nm * f0.y;                        \
        acc.z += nm * f1.x; acc.w += nm * f1.y;                        \
    }

__global__ void k_agg(const __half* __restrict__ H, const float* __restrict__ bias,
                      float4* __restrict__ O, int n, int relu) {
    int gw = (blockIdx.x * blockDim.x + threadIdx.x) >> 5;
    if (gw >= n) return;
    int lane = threadIdx.x & 31;

    float dv = g_dis[gw];
    float sn = dv * dv;                 // self-loop norm = 1/deg
    uint2 sp = *(const uint2*)(H + (size_t)gw * D + lane * 4);
    float2 s0 = u32_as_f2(sp.x);
    float2 s1 = u32_as_f2(sp.y);
    float4 acc = make_float4(sn * s0.x, sn * s0.y, sn * s1.x, sn * s1.y);

    int beg = g_rowptr[gw], end = g_cnt[gw];
    int j = beg;
    for (; j + 8 <= end; j += 8) {
        long long pk0 = g_csr[j + 0];
        long long pk1 = g_csr[j + 1];
        long long pk2 = g_csr[j + 2];
        long long pk3 = g_csr[j + 3];
        long long pk4 = g_csr[j + 4];
        long long pk5 = g_csr[j + 5];
        long long pk6 = g_csr[j + 6];
        long long pk7 = g_csr[j + 7];
        EDGE_BODY(pk0) EDGE_BODY(pk1) EDGE_BODY(pk2) EDGE_BODY(pk3)
        EDGE_BODY(pk4) EDGE_BODY(pk5) EDGE_BODY(pk6) EDGE_BODY(pk7)
    }
    for (; j + 4 <= end; j += 4) {
        long long pk0 = g_csr[j + 0];
        long long pk1 = g_csr[j + 1];
        long long pk2 = g_csr[j + 2];
        long long pk3 = g_csr[j + 3];
        EDGE_BODY(pk0) EDGE_BODY(pk1) EDGE_BODY(pk2) EDGE_BODY(pk3)
    }
    for (; j < end; j++) {
        long long pk = g_csr[j];
        EDGE_BODY(pk)
    }

    float4 bb = ((const float4*)bias)[lane];
    acc.x += bb.x; acc.y += bb.y; acc.z += bb.z; acc.w += bb.w;
    if (relu) {
        acc.x = fmaxf(acc.x, 0.f);
        acc.y = fmaxf(acc.y, 0.f);
        acc.z = fmaxf(acc.z, 0.f);
        acc.w = fmaxf(acc.w, 0.f);
    }
    O[(size_t)gw * D4 + lane] = acc;
}

// ---------------- launch ----------------
extern "C" void kernel_launch(void* const* d_in, const int* in_sizes, int n_in,
                              void* d_out, int out_size) {
    const float* x  = (const float*)d_in[0];
    const int*   ei = (const int*)d_in[1];
    const float* W1 = (const float*)d_in[2];
    const float* b1 = (const float*)d_in[3];
    const float* W2 = (const float*)d_in[4];
    const float* b2 = (const float*)d_in[5];
    const float* W3 = (const float*)d_in[6];
    const float* b3 = (const float*)d_in[7];

    int n = in_sizes[0] / D;
    int e = in_sizes[1] / 2;
    const int* src = ei;
    const int* dst = ei + e;

    void *pcnt = nullptr, *ptail = nullptr, *p0 = nullptr, *pH = nullptr;
    cudaGetSymbolAddress(&pcnt, g_cnt);
    cudaGetSymbolAddress(&ptail, g_tail);
    cudaGetSymbolAddress(&p0, g_buf0);
    cudaGetSymbolAddress(&pH, g_bufH);
    float*  B0 = (float*)p0;
    __half* HB = (__half*)pH;

    // graph preprocessing
    cudaMemsetAsync(pcnt, 0, (size_t)n * sizeof(int));
    cudaMemsetAsync(ptail, 0, sizeof(int));
    k_hist    <<<(e + 255) / 256, 256>>>(dst, e);
    k_disalloc<<<(n + 255) / 256, 256>>>(n);
    k_fill    <<<(e + 255) / 256, 256>>>(src, dst, e);

    size_t smem = (size_t)(D * D + D * XSTR) * sizeof(float);   // ~97.8KB
    cudaFuncSetAttribute(k_gemm, cudaFuncAttributeMaxDynamicSharedMemorySize, (int)smem);

    int gb = (n + GR - 1) / GR;
    int ab = (n + 7) / 8;        // 8 warps / block

    // layer 1
    k_gemm<<<gb, 256, smem>>>(x, W1, HB, n);
    k_agg <<<ab, 256>>>(HB, b1, (float4*)B0, n, 1);
    // layer 2
    k_gemm<<<gb, 256, smem>>>(B0, W2, HB, n);
    k_agg <<<ab, 256>>>(HB, b2, (float4*)B0, n, 1);
    // layer 3
    k_gemm<<<gb, 256, smem>>>(B0, W3, HB, n);
    k_agg <<<ab, 256>>>(HB, b3, (float4*)d_out, n, 0);
}

// round 9
// speedup vs baseline: 1.7187x; 1.1488x over previous
#include <cuda_runtime.h>
#include <cuda_fp16.h>

#define D      128
#define D4     32
#define MAXN   100000
#define MAXE   1600000
#define ASTR   136      // smem A stride in halves (272B: conflict-free frags)

// ---------------- scratch ----------------
__device__ int       g_cnt[MAXN];
__device__ int       g_rowptr[MAXN];
__device__ int       g_fill[MAXN];
__device__ float     g_dis[MAXN];
__device__ int       g_tail;
__device__ long long g_csr[MAXE];
__device__ float     g_buf0[(size_t)MAXN * D];
__device__ __half    g_bufH[(size_t)MAXN * D];
// W in mma-fragment order: idx = ks*512 + nt*32 + lane -> {bhi0,bhi1,blo0,blo1}
__device__ uint4     g_bfrag[4096];

// ---------------- helpers ----------------
__device__ __forceinline__ unsigned int h2_as_u32(__half2 h) {
    return *reinterpret_cast<unsigned int*>(&h);
}
__device__ __forceinline__ float2 u32_as_f2(unsigned int u) {
    return __half22float2(*reinterpret_cast<__half2*>(&u));
}
__device__ __forceinline__ unsigned short bf16_rn(float x) {
    unsigned u = __float_as_uint(x);
    return (unsigned short)((u + 0x7FFF + ((u >> 16) & 1)) >> 16);
}
__device__ __forceinline__ float bf16_to_f(unsigned short h) {
    return __uint_as_float((unsigned)h << 16);
}
__device__ __forceinline__ void mma_bf16(float& d0, float& d1, float& d2, float& d3,
                                         unsigned a0, unsigned a1, unsigned a2, unsigned a3,
                                         unsigned b0, unsigned b1) {
    asm volatile(
        "mma.sync.aligned.m16n8k16.row.col.f32.bf16.bf16.f32 "
        "{%0,%1,%2,%3}, {%4,%5,%6,%7}, {%8,%9}, {%0,%1,%2,%3};"
        : "+f"(d0), "+f"(d1), "+f"(d2), "+f"(d3)
        : "r"(a0), "r"(a1), "r"(a2), "r"(a3), "r"(b0), "r"(b1));
}

// ---------------- graph preprocessing ----------------
__global__ void k_hist(const int* __restrict__ dst, int e) {
    int i = blockIdx.x * blockDim.x + threadIdx.x;
    if (i < e) atomicAdd(&g_cnt[dst[i]], 1);
}

__global__ void k_disalloc(int n) {
    int i = blockIdx.x * blockDim.x + threadIdx.x;
    if (i >= n) return;
    int c = g_cnt[i];
    g_dis[i] = rsqrtf((float)(c + 1));
    int base = atomicAdd(&g_tail, c);
    g_rowptr[i] = base;
    g_fill[i]   = base;
    g_cnt[i]    = base + c;                // reuse as row END
}

__global__ void k_fill(const int* __restrict__ src, const int* __restrict__ dst, int e) {
    int i = blockIdx.x * blockDim.x + threadIdx.x;
    if (i >= e) return;
    int s = src[i], d = dst[i];
    int p = atomicAdd(&g_fill[d], 1);
    float nm = g_dis[s] * g_dis[d];
    long long pk = ((long long)__float_as_int(nm) << 32) | (unsigned int)s;
    g_csr[p] = pk;
}

// ---------------- W -> mma B-fragment pack (per layer, 4096 threads) --------
// B = W (k x n, k = W row). Frag for m16n8k16 col-major B:
//   b0 = {B[k0+2tg, n], B[k0+2tg+1, n]},  b1 = {B[k0+2tg+8, n], B[k0+2tg+9, n]},
//   n = nt*8 + g.  Packed hi pair + lo pair into one uint4.
__global__ void k_wt(const float* __restrict__ W) {
    int t = blockIdx.x * blockDim.x + threadIdx.x;
    if (t >= 4096) return;
    int lane = t & 31;
    int nt   = (t >> 5) & 15;
    int ks   = t >> 9;
    int g = lane >> 2, tg = lane & 3;
    int nn = nt * 8 + g;
    int k0 = ks * 16 + 2 * tg;

    float w00 = W[(k0 + 0) * D + nn];
    float w01 = W[(k0 + 1) * D + nn];
    float w10 = W[(k0 + 8) * D + nn];
    float w11 = W[(k0 + 9) * D + nn];

    unsigned short h00 = bf16_rn(w00), h01 = bf16_rn(w01);
    unsigned short h10 = bf16_rn(w10), h11 = bf16_rn(w11);
    unsigned short l00 = bf16_rn(w00 - bf16_to_f(h00));
    unsigned short l01 = bf16_rn(w01 - bf16_to_f(h01));
    unsigned short l10 = bf16_rn(w10 - bf16_to_f(h10));
    unsigned short l11 = bf16_rn(w11 - bf16_to_f(h11));

    uint4 v;
    v.x = (unsigned)h00 | ((unsigned)h01 << 16);
    v.y = (unsigned)h10 | ((unsigned)h11 << 16);
    v.z = (unsigned)l00 | ((unsigned)l01 << 16);
    v.w = (unsigned)l10 | ((unsigned)l11 << 16);
    g_bfrag[t] = v;
}

// ---------------- HMMA GEMM: H[n,128](fp16) = X[n,128](fp32) @ W -----------
// Split-bf16: 3 passes (Ahi*Bhi + Ahi*Blo + Alo*Bhi), fp32 accum.
// Per CTA: 128 rows; warp w -> rows [16w,16w+16), all 128 cols.
__global__ void __launch_bounds__(256, 2)
k_gemm(const float* __restrict__ X, __half* __restrict__ H, int n) {
    extern __shared__ __half smA[];          // hi [128*ASTR], lo [128*ASTR]
    __half* Ahi = smA;
    __half* Alo = smA + 128 * ASTR;
    int t = threadIdx.x;
    int lane = t & 31, wid = t >> 5;
    int rowBase = blockIdx.x * 128;

    // ---- stage A: split fp32 -> bf16 hi/lo in smem ----
    {
        int r  = t >> 1;
        int ch = (t & 1) * 64;
        bool valid = (rowBase + r) < n;
        const float4* xr = (const float4*)(X + (size_t)(rowBase + r) * D + ch);
#pragma unroll
        for (int i = 0; i < 16; i++) {
            float4 v = valid ? xr[i] : make_float4(0.f, 0.f, 0.f, 0.f);
            unsigned short h0 = bf16_rn(v.x), h1 = bf16_rn(v.y),
                           h2 = bf16_rn(v.z), h3 = bf16_rn(v.w);
            unsigned short l0 = bf16_rn(v.x - bf16_to_f(h0)),
                           l1 = bf16_rn(v.y - bf16_to_f(h1)),
                           l2 = bf16_rn(v.z - bf16_to_f(h2)),
                           l3 = bf16_rn(v.w - bf16_to_f(h3));
            int c = ch + i * 4;
            *(uint2*)(Ahi + r * ASTR + c) =
                make_uint2((unsigned)h0 | ((unsigned)h1 << 16),
                           (unsigned)h2 | ((unsigned)h3 << 16));
            *(uint2*)(Alo + r * ASTR + c) =
                make_uint2((unsigned)l0 | ((unsigned)l1 << 16),
                           (unsigned)l2 | ((unsigned)l3 << 16));
        }
    }
    __syncthreads();

    // ---- mma mainloop ----
    int g = lane >> 2, tg = lane & 3;
    int wr = wid * 16;
    float c0[16], c1[16], c2[16], c3[16];
#pragma unroll
    for (int i = 0; i < 16; i++) { c0[i] = c1[i] = c2[i] = c3[i] = 0.f; }

#pragma unroll
    for (int ks = 0; ks < 8; ks++) {
        int k0 = ks * 16 + 2 * tg;
        unsigned ah0 = *(unsigned*)(Ahi + (wr + g)     * ASTR + k0);
        unsigned ah1 = *(unsigned*)(Ahi + (wr + g + 8) * ASTR + k0);
        unsigned ah2 = *(unsigned*)(Ahi + (wr + g)     * ASTR + k0 + 8);
        unsigned ah3 = *(unsigned*)(Ahi + (wr + g + 8) * ASTR + k0 + 8);
        unsigned al0 = *(unsigned*)(Alo + (wr + g)     * ASTR + k0);
        unsigned al1 = *(unsigned*)(Alo + (wr + g + 8) * ASTR + k0);
        unsigned al2 = *(unsigned*)(Alo + (wr + g)     * ASTR + k0 + 8);
        unsigned al3 = *(unsigned*)(Alo + (wr + g + 8) * ASTR + k0 + 8);
        const uint4* bp = g_bfrag + ks * 512 + lane;
#pragma unroll
        for (int nt = 0; nt < 16; nt++) {
            uint4 b = bp[nt * 32];
            mma_bf16(c0[nt], c1[nt], c2[nt], c3[nt], ah0, ah1, ah2, ah3, b.x, b.y);
            mma_bf16(c0[nt], c1[nt], c2[nt], c3[nt], ah0, ah1, ah2, ah3, b.z, b.w);
            mma_bf16(c0[nt], c1[nt], c2[nt], c3[nt], al0, al1, al2, al3, b.x, b.y);
        }
    }

    // ---- epilogue: fp16 stores (c0/c1 = row g cols 2tg,2tg+1; c2/c3 = row g+8) ----
    int row0 = rowBase + wr + g;
    int row1 = row0 + 8;
    bool v0 = row0 < n, v1 = row1 < n;
    __half* h0p = H + (size_t)row0 * D + 2 * tg;
    __half* h1p = H + (size_t)row1 * D + 2 * tg;
#pragma unroll
    for (int nt = 0; nt < 16; nt++) {
        if (v0) *(unsigned*)(h0p + nt * 8) = h2_as_u32(__floats2half2_rn(c0[nt], c1[nt]));
        if (v1) *(unsigned*)(h1p + nt * 8) = h2_as_u32(__floats2half2_rn(c2[nt], c3[nt]));
    }
}

// ---------------- aggregation (8x/4x unrolled) ----------------
#define EDGE_BODY(pk)                                                  \
    {                                                                  \
        int   si = (int)((pk) & 0xffffffffLL);                         \
        float nm = __int_as_float((int)((pk) >> 32));                  \
        uint2 hp = *(const uint2*)(Hh + (size_t)si * D + lane * 4);    \
        float2 f0 = u32_as_f2(hp.x);                                   \
        float2 f1 = u32_as_f2(hp.y);                                   \
        acc.x += nm * f0.x; acc.y += nm * f0.y;                        \
        acc.z += nm * f1.x; acc.w += nm * f1.y;                        \
    }

__global__ void k_agg(const __half* __restrict__ Hh, const float* __restrict__ bias,
                      float4* __restrict__ O, int n, int relu) {
    int gw = (blockIdx.x * blockDim.x + threadIdx.x) >> 5;
    if (gw >= n) return;
    int lane = threadIdx.x & 31;

    float dv = g_dis[gw];
    float sn = dv * dv;
    uint2 sp = *(const uint2*)(Hh + (size_t)gw * D + lane * 4);
    float2 s0 = u32_as_f2(sp.x);
    float2 s1 = u32_as_f2(sp.y);
    float4 acc = make_float4(sn * s0.x, sn * s0.y, sn * s1.x, sn * s1.y);

    int beg = g_rowptr[gw], end = g_cnt[gw];
    int j = beg;
    for (; j + 8 <= end; j += 8) {
        long long pk0 = g_csr[j + 0], pk1 = g_csr[j + 1];
        long long pk2 = g_csr[j + 2], pk3 = g_csr[j + 3];
        long long pk4 = g_csr[j + 4], pk5 = g_csr[j + 5];
        long long pk6 = g_csr[j + 6], pk7 = g_csr[j + 7];
        EDGE_BODY(pk0) EDGE_BODY(pk1) EDGE_BODY(pk2) EDGE_BODY(pk3)
        EDGE_BODY(pk4) EDGE_BODY(pk5) EDGE_BODY(pk6) EDGE_BODY(pk7)
    }
    for (; j + 4 <= end; j += 4) {
        long long pk0 = g_csr[j + 0], pk1 = g_csr[j + 1];
        long long pk2 = g_csr[j + 2], pk3 = g_csr[j + 3];
        EDGE_BODY(pk0) EDGE_BODY(pk1) EDGE_BODY(pk2) EDGE_BODY(pk3)
    }
    for (; j < end; j++) { long long pk = g_csr[j]; EDGE_BODY(pk) }

    float4 bb = ((const float4*)bias)[lane];
    acc.x += bb.x; acc.y += bb.y; acc.z += bb.z; acc.w += bb.w;
    if (relu) {
        acc.x = fmaxf(acc.x, 0.f); acc.y = fmaxf(acc.y, 0.f);
        acc.z = fmaxf(acc.z, 0.f); acc.w = fmaxf(acc.w, 0.f);
    }
    O[(size_t)gw * D4 + lane] = acc;
}

// ---------------- launch ----------------
extern "C" void kernel_launch(void* const* d_in, const int* in_sizes, int n_in,
                              void* d_out, int out_size) {
    const float* x  = (const float*)d_in[0];
    const int*   ei = (const int*)d_in[1];
    const float* W1 = (const float*)d_in[2];
    const float* b1 = (const float*)d_in[3];
    const float* W2 = (const float*)d_in[4];
    const float* b2 = (const float*)d_in[5];
    const float* W3 = (const float*)d_in[6];
    const float* b3 = (const float*)d_in[7];

    int n = in_sizes[0] / D;
    int e = in_sizes[1] / 2;
    const int* src = ei;
    const int* dst = ei + e;

    void *pcnt = nullptr, *ptail = nullptr, *p0 = nullptr, *pH = nullptr;
    cudaGetSymbolAddress(&pcnt, g_cnt);
    cudaGetSymbolAddress(&ptail, g_tail);
    cudaGetSymbolAddress(&p0, g_buf0);
    cudaGetSymbolAddress(&pH, g_bufH);
    float*  B0 = (float*)p0;
    __half* HB = (__half*)pH;

    cudaMemsetAsync(pcnt, 0, (size_t)n * sizeof(int));
    cudaMemsetAsync(ptail, 0, sizeof(int));
    k_hist    <<<(e + 255) / 256, 256>>>(dst, e);
    k_disalloc<<<(n + 255) / 256, 256>>>(n);
    k_fill    <<<(e + 255) / 256, 256>>>(src, dst, e);

    size_t smem = (size_t)2 * 128 * ASTR * sizeof(__half);   // 69632 B
    cudaFuncSetAttribute(k_gemm, cudaFuncAttributeMaxDynamicSharedMemorySize, (int)smem);

    int gb = (n + 127) / 128;
    int ab = (n + 7) / 8;

    // layer 1
    k_wt  <<<16, 256>>>(W1);
    k_gemm<<<gb, 256, smem>>>(x, HB, n);
    k_agg <<<ab, 256>>>(HB, b1, (float4*)B0, n, 1);
    // layer 2
    k_wt  <<<16, 256>>>(W2);
    k_gemm<<<gb, 256, smem>>>(B0, HB, n);
    k_agg <<<ab, 256>>>(HB, b2, (float4*)B0, n, 1);
    // layer 3
    k_wt  <<<16, 256>>>(W3);
    k_gemm<<<gb, 256, smem>>>(B0, HB, n);
    k_agg <<<ab, 256>>>(HB, b3, (float4*)d_out, n, 0);
}